// round 13
// baseline (speedup 1.0000x reference)
#include <cuda_runtime.h>
#include <cuda_bf16.h>
#include <cstdint>

// Problem constants: N=50000, E=250000, D=300, L=5
#define D_    300
#define TWOD_ 600
#define NMAX  50000
#define DEG_CAP 64
#define KPAD1 320   // 300 -> 10 chunks of 32
#define KPAD2 608   // 600 -> 19 chunks of 32
#define KP2_1 (KPAD1 / 2)   // 160 packed pairs
#define KP2_2 (KPAD2 / 2)   // 304 packed pairs
#define NCP1  640   // 600 -> 5 tiles of 128
#define NCP2  384   // 300 -> 3 tiles of 128

// GEMM tiling (bf16 pairs: one uint32 = 2 bf16 along k)
#define BM 128
#define BN 128
#define BK 32
#define STRU 16                 // smem row stride in uint32 (swizzled, no pad)
#define TSZU (128 * STRU)       // 2048 u32 per tile
#define AHO_U 0
#define ALO_U TSZU
#define BHO_U (2 * TSZU)
#define BLO_U (3 * TSZU)
#define BUFSZ_U (4 * TSZU)      // 8192 u32 = 32KB per stage
#define GEMM_SMEM (2 * BUFSZ_U * 4)   // 65536 B; 3 CTAs/SM = 192KB

// ---- static scratch (no allocations allowed) ----
__device__ float g_h [NMAX * D_];
__device__ float g_h1[NMAX * TWOD_];
__device__ float g_z2[NMAX * D_];
__device__ float g_cs[TWOD_];
__device__ float g_cq[TWOD_];
__device__ float g_bnA[TWOD_];
__device__ float g_bnB[TWOD_];
__device__ int   g_fill[NMAX];
__device__ int   g_eid [NMAX * DEG_CAP];
// packed split activations (A operands), k-permuted bf16x2
__device__ uint32_t g_a1h[NMAX * KP2_1];
__device__ uint32_t g_a1l[NMAX * KP2_1];
__device__ uint32_t g_a2h[NMAX * KP2_2];
__device__ uint32_t g_a2l[NMAX * KP2_2];
// pre-transposed + bf16-split + pair-permuted + padded weights
__device__ uint32_t g_w1h[NCP1 * KP2_1];
__device__ uint32_t g_w1l[NCP1 * KP2_1];
__device__ uint32_t g_w2h[NCP2 * KP2_2];
__device__ uint32_t g_w2l[NCP2 * KP2_2];

// ============================================================
// helpers (baseline PTX only — safe under virtual arch compute_103)
// ============================================================
__device__ __forceinline__ uint32_t smem_u32(const void* p) {
    uint32_t a;
    asm("{ .reg .u64 t; cvta.to.shared.u64 t, %1; cvt.u32.u64 %0, t; }"
        : "=r"(a) : "l"(p));
    return a;
}
__device__ __forceinline__ void cp16p(uint32_t dst, const void* src, bool pred) {
    int sz = pred ? 16 : 0;
    asm volatile("cp.async.cg.shared.global [%0], [%1], 16, %2;"
                 :: "r"(dst), "l"(src), "r"(sz) : "memory");
}
__device__ __forceinline__ void cp_commit() {
    asm volatile("cp.async.commit_group;" ::: "memory");
}
__device__ __forceinline__ void cp_wait0() {
    asm volatile("cp.async.wait_group 0;" ::: "memory");
}
__device__ __forceinline__ void bf16s(float v, uint16_t& h, uint16_t& l) {
    __nv_bfloat16 hb = __float2bfloat16(v);
    float r = v - __bfloat162float(hb);
    __nv_bfloat16 lb = __float2bfloat16(r);
    h = __bfloat16_as_ushort(hb);
    l = __bfloat16_as_ushort(lb);
}
__device__ __forceinline__ void mma16(float* c,
                                      uint32_t a0, uint32_t a1, uint32_t a2, uint32_t a3,
                                      uint32_t b0, uint32_t b1) {
    asm volatile(
        "mma.sync.aligned.m16n8k16.row.col.f32.bf16.bf16.f32 "
        "{%0,%1,%2,%3}, {%4,%5,%6,%7}, {%8,%9}, {%0,%1,%2,%3};"
        : "+f"(c[0]), "+f"(c[1]), "+f"(c[2]), "+f"(c[3])
        : "r"(a0), "r"(a1), "r"(a2), "r"(a3), "r"(b0), "r"(b1));
}
// pack pair (a,b) at logical pair index kp2 into permuted split arrays
__device__ __forceinline__ void packw(uint32_t* __restrict__ Wh,
                                      uint32_t* __restrict__ Wl,
                                      size_t rowbase, int kp2, float a, float b) {
    int c  = kp2 >> 4;
    int pp = kp2 & 15;
    int pos = ((pp >> 3) << 3) + 2 * (pp & 3) + ((pp & 7) >> 2);
    size_t idx = rowbase + c * 16 + pos;
    uint16_t ha, la, hb, lb;
    bf16s(a, ha, la);
    bf16s(b, hb, lb);
    Wh[idx] = (uint32_t)ha | ((uint32_t)hb << 16);
    Wl[idx] = (uint32_t)la | ((uint32_t)lb << 16);
}

// ============================================================
// Weight prep; zeroes fused stats (+ degree counters on first call)
// ============================================================
__global__ void k_wprep(const float* __restrict__ W, uint32_t* __restrict__ Wh,
                        uint32_t* __restrict__ Wl, int K, int NC, int Kp2,
                        int NCpad, int zfill)
{
    int idx = blockIdx.x * blockDim.x + threadIdx.x;
    if (idx < TWOD_) { g_cs[idx] = 0.f; g_cq[idx] = 0.f; }
    if (zfill && idx < NMAX) g_fill[idx] = 0;
    if (idx >= NCpad * Kp2) return;
    int n   = idx / Kp2;
    int kp2 = idx - n * Kp2;
    int k0 = 2 * kp2;
    float v0 = (k0 < K && n < NC)     ? W[k0 * NC + n]       : 0.f;
    float v1 = (k0 + 1 < K && n < NC) ? W[(k0 + 1) * NC + n] : 0.f;
    packw(Wh, Wl, (size_t)n * Kp2, kp2, v0, v1);
}

// ============================================================
// Atom encoder + edge-bucket scatter (counters pre-zeroed by wprep)
// ============================================================
__global__ void k_atom(const int* __restrict__ x, const float* __restrict__ emb,
                       const int* __restrict__ ei, int n, int E_)
{
    int idx = blockIdx.x * blockDim.x + threadIdx.x;
    if (idx < E_) {
        int dst = ei[E_ + idx];
        int p = atomicAdd(&g_fill[dst], 1);
        if (p < DEG_CAP) g_eid[dst * DEG_CAP + p] = idx;
    }
    if (idx >= n * D_) return;
    int node = idx / D_;
    int d    = idx - node * D_;
    const int* xr = x + node * 9;
    float s = 0.f;
#pragma unroll
    for (int i = 0; i < 9; i++)
        s += emb[(i * 128 + xr[i]) * D_ + d];
    g_h[idx] = s;
}

// ============================================================
// Aggregation (atomic-free, warp per dst node); reads g_h (pre-applied),
// emits z directly as packed split bf16 (GEMM1's A operand).
// ============================================================
__global__ void k_aggregate(const int* __restrict__ ei, const int* __restrict__ ea,
                            const float* __restrict__ bond,
                            const float* __restrict__ eps, int n, int layer)
{
    int w    = (blockIdx.x * blockDim.x + threadIdx.x) >> 5;
    int lane = threadIdx.x & 31;
    if (w >= n) return;
    int deg = g_fill[w];
    if (deg > DEG_CAP) deg = DEG_CAP;

    const float4* h4 = (const float4*)g_h;
    const float4* bl = (const float4*)(bond + (size_t)layer * 3 * 16 * D_);
    const int l2 = lane + 32, l3 = lane + 64;
    float4 a0 = make_float4(0.f, 0.f, 0.f, 0.f), a1 = a0, a2 = a0;

    const int* bucket = g_eid + (size_t)w * DEG_CAP;
    for (int p = 0; p < deg; ++p) {
        int eid = bucket[p];
        int src = ei[eid];
        int t3  = eid * 3;
        int c0 = ea[t3], c1 = ea[t3 + 1], c2 = ea[t3 + 2];
        const float4* hr = h4 + (size_t)src * 75;
        const float4* r0 = bl + c0 * 75;
        const float4* r1 = bl + (16 + c1) * 75;
        const float4* r2 = bl + (32 + c2) * 75;
        float4 h, e0, e1, e2;
        h = hr[lane]; e0 = r0[lane]; e1 = r1[lane]; e2 = r2[lane];
        a0.x += fmaxf(h.x + e0.x + e1.x + e2.x, 0.f);
        a0.y += fmaxf(h.y + e0.y + e1.y + e2.y, 0.f);
        a0.z += fmaxf(h.z + e0.z + e1.z + e2.z, 0.f);
        a0.w += fmaxf(h.w + e0.w + e1.w + e2.w, 0.f);
        h = hr[l2]; e0 = r0[l2]; e1 = r1[l2]; e2 = r2[l2];
        a1.x += fmaxf(h.x + e0.x + e1.x + e2.x, 0.f);
        a1.y += fmaxf(h.y + e0.y + e1.y + e2.y, 0.f);
        a1.z += fmaxf(h.z + e0.z + e1.z + e2.z, 0.f);
        a1.w += fmaxf(h.w + e0.w + e1.w + e2.w, 0.f);
        if (l3 < 75) {
            h = hr[l3]; e0 = r0[l3]; e1 = r1[l3]; e2 = r2[l3];
            a2.x += fmaxf(h.x + e0.x + e1.x + e2.x, 0.f);
            a2.y += fmaxf(h.y + e0.y + e1.y + e2.y, 0.f);
            a2.z += fmaxf(h.z + e0.z + e1.z + e2.z, 0.f);
            a2.w += fmaxf(h.w + e0.w + e1.w + e2.w, 0.f);
        }
    }
    float ep = 1.f + eps[layer];
    const float4* hv = h4 + (size_t)w * 75;
    const size_t rowbase = (size_t)w * KP2_1;
    float4 h, o;
    h = hv[lane];
    o.x = fmaf(ep, h.x, a0.x); o.y = fmaf(ep, h.y, a0.y);
    o.z = fmaf(ep, h.z, a0.z); o.w = fmaf(ep, h.w, a0.w);
    packw(g_a1h, g_a1l, rowbase, 2 * lane,     o.x, o.y);
    packw(g_a1h, g_a1l, rowbase, 2 * lane + 1, o.z, o.w);
    h = hv[l2];
    o.x = fmaf(ep, h.x, a1.x); o.y = fmaf(ep, h.y, a1.y);
    o.z = fmaf(ep, h.z, a1.z); o.w = fmaf(ep, h.w, a1.w);
    packw(g_a1h, g_a1l, rowbase, 2 * l2,     o.x, o.y);
    packw(g_a1h, g_a1l, rowbase, 2 * l2 + 1, o.z, o.w);
    if (l3 < 75) {
        h = hv[l3];
        o.x = fmaf(ep, h.x, a2.x); o.y = fmaf(ep, h.y, a2.y);
        o.z = fmaf(ep, h.z, a2.z); o.w = fmaf(ep, h.w, a2.w);
        packw(g_a1h, g_a1l, rowbase, 2 * l3,     o.x, o.y);
        packw(g_a1h, g_a1l, rowbase, 2 * l3 + 1, o.z, o.w);
    }
    if (lane < KP2_1 - 150)
        packw(g_a1h, g_a1l, rowbase, 150 + lane, 0.f, 0.f);
}

// ============================================================
// A-split for GEMM2: relu(BN1(h1)) -> packed split bf16
// ============================================================
__global__ void k_asplit(const float* __restrict__ X, int M, int K, int Kp2)
{
    int idx = blockIdx.x * blockDim.x + threadIdx.x;
    if (idx >= M * Kp2) return;
    int m   = idx / Kp2;
    int kp2 = idx - m * Kp2;
    int k0  = 2 * kp2;
    float a = 0.f, b = 0.f;
    if (k0 < K) {
        float2 v = *(const float2*)(X + (size_t)m * K + k0);
        a = fmaxf(fmaf(v.x, g_bnA[k0],     g_bnB[k0]),     0.f);
        b = fmaxf(fmaf(v.y, g_bnA[k0 + 1], g_bnB[k0 + 1]), 0.f);
    }
    packw(g_a2h, g_a2l, (size_t)m * Kp2, kp2, a, b);
}

// ============================================================
// 3xBF16 mma.sync GEMM: 512 threads, 16 warps (4x4), 32x32 warp tiles,
// swizzled smem (no pad), double-buffered, 3 CTAs/SM, fused stats.
// ============================================================
__global__ void __launch_bounds__(512, 3) k_gemm_mma(
    const uint32_t* __restrict__ Ah, const uint32_t* __restrict__ Al,
    const uint32_t* __restrict__ Bh, const uint32_t* __restrict__ Bl,
    const float* __restrict__ bias, float* __restrict__ C,
    int M, int Kpad, int NC)
{
    extern __shared__ uint32_t smu[];
    const int tid = threadIdx.x;
    const int wid = tid >> 5, lid = tid & 31;
    const int g = lid >> 2, t4 = lid & 3;
    const int wm = wid >> 2, wn = wid & 3;
    const int bm = blockIdx.y * BM, bn = blockIdx.x * BN;
    const int nch = Kpad / BK;
    const int Kp2 = Kpad >> 1;
    const bool wActive = (bn + wn * 32) < NC;   // dead-warp skip (padded N)

    // loader mapping: each thread one 16B per tile: row=tid>>2, c4=tid&3
    const int lrow = tid >> 2;
    const int lc4  = tid & 3;
    const int c4s  = lc4 ^ (lrow & 3);          // swizzle
    const bool aOk = (bm + lrow) < M;
    const uint32_t* AhR = Ah + (size_t)(bm + lrow) * Kp2 + lc4 * 4;
    const uint32_t* AlR = Al + (size_t)(bm + lrow) * Kp2 + lc4 * 4;
    const uint32_t* BhR = Bh + (size_t)(bn + lrow) * Kp2 + lc4 * 4;
    const uint32_t* BlR = Bl + (size_t)(bn + lrow) * Kp2 + lc4 * 4;
    const uint32_t sm32 = smem_u32(smu);
    const uint32_t st_off = (uint32_t)((lrow * STRU + c4s * 4) * 4);
    const uint32_t cpAH = sm32 + AHO_U * 4 + st_off;
    const uint32_t cpAL = sm32 + ALO_U * 4 + st_off;
    const uint32_t cpBH = sm32 + BHO_U * 4 + st_off;
    const uint32_t cpBL = sm32 + BLO_U * 4 + st_off;

    float acc[2][4][4];
#pragma unroll
    for (int i = 0; i < 2; i++)
#pragma unroll
        for (int j = 0; j < 4; j++)
#pragma unroll
            for (int k = 0; k < 4; k++) acc[i][j][k] = 0.f;

#define CP_CHUNK(BUFB, C0)                                                \
    {                                                                     \
        const uint32_t bo = (uint32_t)((BUFB) * 4);                       \
        const int co = (C0) * 16;                                         \
        cp16p(cpAH + bo, AhR + co, aOk);                                  \
        cp16p(cpAL + bo, AlR + co, aOk);                                  \
        cp16p(cpBH + bo, BhR + co, true);                                 \
        cp16p(cpBL + bo, BlR + co, true);                                 \
    }

    CP_CHUNK(0, 0);
    cp_commit();
    cp_wait0();
    __syncthreads();

    for (int c = 0; c < nch; ++c) {
        const int bufc = (c & 1) * BUFSZ_U;
        const int bufn = ((c + 1) & 1) * BUFSZ_U;
        if (c + 1 < nch) {
            CP_CHUNK(bufn, c + 1);
            cp_commit();
        }
        if (wActive) {
            const uint32_t* aH = smu + bufc + AHO_U;
            const uint32_t* aL = smu + bufc + ALO_U;
            const uint32_t* bH = smu + bufc + BHO_U;
            const uint32_t* bL = smu + bufc + BLO_U;
#pragma unroll
            for (int s = 0; s < 2; ++s) {
                const int c2s = (s * 4 + t4) ^ (2 * (g & 3));  // swizzled uint2 idx
                const int wo  = 2 * c2s;
                uint2 fbh[4], fbl[4];
#pragma unroll
                for (int nt = 0; nt < 4; ++nt) {
                    const int n = wn * 32 + nt * 8 + g;
                    fbh[nt] = *(const uint2*)(bH + n * STRU + wo);
                    fbl[nt] = *(const uint2*)(bL + n * STRU + wo);
                }
                uint2 ah0[2], ah1[2], al0[2], al1[2];
#pragma unroll
                for (int mt = 0; mt < 2; ++mt) {
                    const int r0 = wm * 32 + mt * 16 + g;
                    ah0[mt] = *(const uint2*)(aH + r0 * STRU + wo);
                    ah1[mt] = *(const uint2*)(aH + (r0 + 8) * STRU + wo);
                    al0[mt] = *(const uint2*)(aL + r0 * STRU + wo);
                    al1[mt] = *(const uint2*)(aL + (r0 + 8) * STRU + wo);
                }
#pragma unroll
                for (int mt = 0; mt < 2; ++mt)
#pragma unroll
                    for (int nt = 0; nt < 4; ++nt)
                        mma16(acc[mt][nt], ah0[mt].x, ah1[mt].x, ah0[mt].y, ah1[mt].y,
                              fbh[nt].x, fbh[nt].y);
#pragma unroll
                for (int mt = 0; mt < 2; ++mt)
#pragma unroll
                    for (int nt = 0; nt < 4; ++nt)
                        mma16(acc[mt][nt], ah0[mt].x, ah1[mt].x, ah0[mt].y, ah1[mt].y,
                              fbl[nt].x, fbl[nt].y);
#pragma unroll
                for (int mt = 0; mt < 2; ++mt)
#pragma unroll
                    for (int nt = 0; nt < 4; ++nt)
                        mma16(acc[mt][nt], al0[mt].x, al1[mt].x, al0[mt].y, al1[mt].y,
                              fbh[nt].x, fbh[nt].y);
            }
        }
        if (c + 1 < nch) cp_wait0();
        __syncthreads();
    }

    // ---- epilogue: +bias, stores, fused column stats (skip dead warps) ----
    if (wActive) {
#pragma unroll
        for (int nt = 0; nt < 4; ++nt) {
            const int col = bn + wn * 32 + nt * 8 + 2 * t4;
            const bool cok = col < NC;
            const float b0 = cok ? bias[col]     : 0.f;
            const float b1 = cok ? bias[col + 1] : 0.f;
            float s0 = 0.f, s1 = 0.f, q0 = 0.f, q1 = 0.f;
#pragma unroll
            for (int mt = 0; mt < 2; ++mt) {
                const int r0g = bm + wm * 32 + mt * 16 + g;
                const float* a4 = acc[mt][nt];
                if (cok && r0g < M) {
                    float v0 = a4[0] + b0, v1 = a4[1] + b1;
                    *(float2*)(C + (size_t)r0g * NC + col) = make_float2(v0, v1);
                    s0 += v0; q0 += v0 * v0;
                    s1 += v1; q1 += v1 * v1;
                }
                if (cok && r0g + 8 < M) {
                    float v2 = a4[2] + b0, v3 = a4[3] + b1;
                    *(float2*)(C + (size_t)(r0g + 8) * NC + col) = make_float2(v2, v3);
                    s0 += v2; q0 += v2 * v2;
                    s1 += v3; q1 += v3 * v3;
                }
            }
#pragma unroll
            for (int m = 4; m <= 16; m <<= 1) {
                s0 += __shfl_xor_sync(0xffffffffu, s0, m);
                s1 += __shfl_xor_sync(0xffffffffu, s1, m);
                q0 += __shfl_xor_sync(0xffffffffu, q0, m);
                q1 += __shfl_xor_sync(0xffffffffu, q1, m);
            }
            if (cok && g == 0) {
                atomicAdd(&g_cs[col],     s0);
                atomicAdd(&g_cq[col],     q0);
                atomicAdd(&g_cs[col + 1], s1);
                atomicAdd(&g_cq[col + 1], q1);
            }
        }
    }
#undef CP_CHUNK
}

// ============================================================
// BN finalize + apply
// ============================================================
__global__ void k_finalize(const float* __restrict__ g, const float* __restrict__ b,
                           int M, int C)
{
    int c = threadIdx.x;
    float mean = g_cs[c] / (float)M;
    float var  = g_cq[c] / (float)M - mean * mean;
    float a = g[c] * rsqrtf(var + 1e-5f);
    g_bnA[c] = a;
    g_bnB[c] = fmaf(-mean, a, b[c]);
}

__global__ void k_apply(int do_relu, int n, float* __restrict__ out)
{
    int idx = blockIdx.x * blockDim.x + threadIdx.x;
    if (idx >= n * D_) return;
    int c = idx % D_;
    float v = fmaf(g_z2[idx], g_bnA[c], g_bnB[c]);
    if (do_relu) v = fmaxf(v, 0.f);
    if (out) out[idx] = v;
    else     g_h[idx] = v;
}

// ============================================================
// Launch
// ============================================================
extern "C" void kernel_launch(void* const* d_in, const int* in_sizes, int n_in,
                              void* d_out, int out_size)
{
    const int*   x     = (const int*)  d_in[0];
    const int*   ei    = (const int*)  d_in[1];
    const int*   ea    = (const int*)  d_in[2];
    const float* atom  = (const float*)d_in[3];
    const float* bond  = (const float*)d_in[4];
    const float* eps   = (const float*)d_in[5];
    const float* W1    = (const float*)d_in[6];
    const float* b1    = (const float*)d_in[7];
    const float* g1    = (const float*)d_in[8];
    const float* be1   = (const float*)d_in[9];
    const float* W2    = (const float*)d_in[10];
    const float* b2    = (const float*)d_in[11];
    const float* gamma = (const float*)d_in[12];
    const float* beta  = (const float*)d_in[13];
    float* out = (float*)d_out;

    const int N = in_sizes[0] / 9;
    const int E = in_sizes[1] / 2;

    float *ph1, *pz2;
    uint32_t *pa1h, *pa1l, *pa2h, *pa2l, *pw1h, *pw1l, *pw2h, *pw2l;
    cudaGetSymbolAddress((void**)&ph1,  g_h1);
    cudaGetSymbolAddress((void**)&pz2,  g_z2);
    cudaGetSymbolAddress((void**)&pa1h, g_a1h);
    cudaGetSymbolAddress((void**)&pa1l, g_a1l);
    cudaGetSymbolAddress((void**)&pa2h, g_a2h);
    cudaGetSymbolAddress((void**)&pa2l, g_a2l);
    cudaGetSymbolAddress((void**)&pw1h, g_w1h);
    cudaGetSymbolAddress((void**)&pw1l, g_w1l);
    cudaGetSymbolAddress((void**)&pw2h, g_w2h);
    cudaGetSymbolAddress((void**)&pw2l, g_w2l);

    cudaFuncSetAttribute(k_gemm_mma, cudaFuncAttributeMaxDynamicSharedMemorySize,
                         GEMM_SMEM);

    const int TPB = 256;
    const int node_grid = (N * D_ + TPB - 1) / TPB;
    const int agg_grid  = (N + 7) / 8;
    const int asp_grid  = (N * KP2_2 + TPB - 1) / TPB;
    const dim3 g1grid(NCP1 / BN, (N + BM - 1) / BM);
    const dim3 g2grid(NCP2 / BN, (N + BM - 1) / BM);
    const int wp1 = (NCP1 * KP2_1 + TPB - 1) / TPB;
    const int wp2 = (NCP2 * KP2_2 + TPB - 1) / TPB;

    // #0: W1 prep (also zeroes stats + degree counters)
    k_wprep<<<wp1, TPB>>>(W1, pw1h, pw1l, D_, TWOD_, KP2_1, NCP1, 1);
    // #1: atom encoder + edge bucketing
    k_atom<<<node_grid, TPB>>>(x, atom, ei, N, E);

    for (int l = 0; l < 5; ++l) {
        if (l > 0)
            k_wprep<<<wp1, TPB>>>(W1 + (size_t)l * D_ * TWOD_, pw1h, pw1l,
                                  D_, TWOD_, KP2_1, NCP1, 0);
        // #2 (l=0): aggregation -> packed A1
        k_aggregate<<<agg_grid, TPB>>>(ei, ea, bond, eps, N, l);
        // #3 (l=0): h1 = z @ W1 + b1  (+ fused BN1 stats) — profiled slot
        k_gemm_mma<<<g1grid, 512, GEMM_SMEM>>>(pa1h, pa1l, pw1h, pw1l,
                                               b1 + l * TWOD_, ph1,
                                               N, KPAD1, TWOD_);
        k_finalize<<<1, TWOD_>>>(g1 + l * TWOD_, be1 + l * TWOD_, N, TWOD_);
        // A2 = relu(BN1(h1)) packed split
        k_asplit<<<asp_grid, TPB>>>(ph1, N, TWOD_, KP2_2);
        k_wprep<<<wp2, TPB>>>(W2 + (size_t)l * TWOD_ * D_, pw2h, pw2l,
                              TWOD_, D_, KP2_2, NCP2, 0);
        // z2 = A2 @ W2 + b2  (+ fused BN2 stats)
        k_gemm_mma<<<g2grid, 512, GEMM_SMEM>>>(pa2h, pa2l, pw2h, pw2l,
                                               b2 + l * D_, pz2,
                                               N, KPAD2, D_);
        k_finalize<<<1, D_>>>(gamma + l * D_, beta + l * D_, N, D_);
        // h = BN2(z2) (+relu) for next layer, or final output
        if (l < 4)
            k_apply<<<node_grid, TPB>>>(1, N, nullptr);
        else
            k_apply<<<node_grid, TPB>>>(0, N, out);
    }
}

// round 14
// speedup vs baseline: 2.8308x; 2.8308x over previous
#include <cuda_runtime.h>
#include <cuda_bf16.h>
#include <cstdint>

// Problem constants: N=50000, E=250000, D=300, L=5
#define D_    300
#define TWOD_ 600
#define NMAX  50000
#define DEG_CAP 64
#define KPAD1 320   // 300 -> 10 chunks of 32
#define KPAD2 608   // 600 -> 19 chunks of 32
#define KP2_1 (KPAD1 / 2)   // 160 packed pairs
#define KP2_2 (KPAD2 / 2)   // 304 packed pairs
#define NCP1  640   // 600 -> 10 tiles of 64
#define NCP2  320   // 300 -> 5 tiles of 64

// GEMM tiling (bf16 pairs: one uint32 = 2 bf16 along k)
#define BM 128
#define BN 64
#define BK 32
#define STRU 16                 // smem row stride in uint32 (swizzled)
#define AHO_U 0
#define ALO_U 2048              // A tile: 128*16 u32
#define BHO_U 4096
#define BLO_U 5120              // B tile: 64*16 u32
#define BUFSZ_U 6144            // 24KB per stage
#define GEMM_SMEM (2 * BUFSZ_U * 4)   // 49152 B; 3 CTAs/SM = 144KB

// ---- static scratch (no allocations allowed) ----
__device__ float g_h [NMAX * D_];
__device__ float g_h1[NMAX * TWOD_];
__device__ float g_z2[NMAX * D_];
__device__ float g_cs[TWOD_];
__device__ float g_cq[TWOD_];
__device__ float g_bnA[TWOD_];
__device__ float g_bnB[TWOD_];
__device__ int   g_fill[NMAX];
__device__ int   g_eid [NMAX * DEG_CAP];
// packed split activations (A operands), k-permuted bf16x2
__device__ uint32_t g_a1h[NMAX * KP2_1];
__device__ uint32_t g_a1l[NMAX * KP2_1];
__device__ uint32_t g_a2h[NMAX * KP2_2];
__device__ uint32_t g_a2l[NMAX * KP2_2];
// pre-transposed + bf16-split + pair-permuted + padded weights
__device__ uint32_t g_w1h[NCP1 * KP2_1];
__device__ uint32_t g_w1l[NCP1 * KP2_1];
__device__ uint32_t g_w2h[NCP2 * KP2_2];
__device__ uint32_t g_w2l[NCP2 * KP2_2];

// ============================================================
// helpers (baseline PTX only — safe under virtual arch compute_103)
// ============================================================
__device__ __forceinline__ uint32_t smem_u32(const void* p) {
    uint32_t a;
    asm("{ .reg .u64 t; cvta.to.shared.u64 t, %1; cvt.u32.u64 %0, t; }"
        : "=r"(a) : "l"(p));
    return a;
}
__device__ __forceinline__ void cp16p(uint32_t dst, const void* src, bool pred) {
    int sz = pred ? 16 : 0;
    asm volatile("cp.async.cg.shared.global [%0], [%1], 16, %2;"
                 :: "r"(dst), "l"(src), "r"(sz) : "memory");
}
__device__ __forceinline__ void cp_commit() {
    asm volatile("cp.async.commit_group;" ::: "memory");
}
__device__ __forceinline__ void cp_wait0() {
    asm volatile("cp.async.wait_group 0;" ::: "memory");
}
__device__ __forceinline__ void bf16s(float v, uint16_t& h, uint16_t& l) {
    __nv_bfloat16 hb = __float2bfloat16(v);
    float r = v - __bfloat162float(hb);
    __nv_bfloat16 lb = __float2bfloat16(r);
    h = __bfloat16_as_ushort(hb);
    l = __bfloat16_as_ushort(lb);
}
__device__ __forceinline__ void mma16(float* c,
                                      uint32_t a0, uint32_t a1, uint32_t a2, uint32_t a3,
                                      uint32_t b0, uint32_t b1) {
    asm volatile(
        "mma.sync.aligned.m16n8k16.row.col.f32.bf16.bf16.f32 "
        "{%0,%1,%2,%3}, {%4,%5,%6,%7}, {%8,%9}, {%0,%1,%2,%3};"
        : "+f"(c[0]), "+f"(c[1]), "+f"(c[2]), "+f"(c[3])
        : "r"(a0), "r"(a1), "r"(a2), "r"(a3), "r"(b0), "r"(b1));
}
// pack pair (a,b) at logical pair index kp2 into permuted split arrays
__device__ __forceinline__ void packw(uint32_t* __restrict__ Wh,
                                      uint32_t* __restrict__ Wl,
                                      size_t rowbase, int kp2, float a, float b) {
    int c  = kp2 >> 4;
    int pp = kp2 & 15;
    int pos = ((pp >> 3) << 3) + 2 * (pp & 3) + ((pp & 7) >> 2);
    size_t idx = rowbase + c * 16 + pos;
    uint16_t ha, la, hb, lb;
    bf16s(a, ha, la);
    bf16s(b, hb, lb);
    Wh[idx] = (uint32_t)ha | ((uint32_t)hb << 16);
    Wl[idx] = (uint32_t)la | ((uint32_t)lb << 16);
}

// ============================================================
// Weight prep; zeroes fused stats (+ degree counters on first call)
// ============================================================
__global__ void k_wprep(const float* __restrict__ W, uint32_t* __restrict__ Wh,
                        uint32_t* __restrict__ Wl, int K, int NC, int Kp2,
                        int NCpad, int zfill)
{
    int idx = blockIdx.x * blockDim.x + threadIdx.x;
    if (idx < TWOD_) { g_cs[idx] = 0.f; g_cq[idx] = 0.f; }
    if (zfill && idx < NMAX) g_fill[idx] = 0;
    if (idx >= NCpad * Kp2) return;
    int n   = idx / Kp2;
    int kp2 = idx - n * Kp2;
    int k0 = 2 * kp2;
    float v0 = (k0 < K && n < NC)     ? W[k0 * NC + n]       : 0.f;
    float v1 = (k0 + 1 < K && n < NC) ? W[(k0 + 1) * NC + n] : 0.f;
    packw(Wh, Wl, (size_t)n * Kp2, kp2, v0, v1);
}

// ============================================================
// Atom encoder + edge-bucket scatter (counters pre-zeroed by wprep)
// ============================================================
__global__ void k_atom(const int* __restrict__ x, const float* __restrict__ emb,
                       const int* __restrict__ ei, int n, int E_)
{
    int idx = blockIdx.x * blockDim.x + threadIdx.x;
    if (idx < E_) {
        int dst = ei[E_ + idx];
        int p = atomicAdd(&g_fill[dst], 1);
        if (p < DEG_CAP) g_eid[dst * DEG_CAP + p] = idx;
    }
    if (idx >= n * D_) return;
    int node = idx / D_;
    int d    = idx - node * D_;
    const int* xr = x + node * 9;
    float s = 0.f;
#pragma unroll
    for (int i = 0; i < 9; i++)
        s += emb[(i * 128 + xr[i]) * D_ + d];
    g_h[idx] = s;
}

// ============================================================
// Aggregation (atomic-free, warp per dst node); reads g_h,
// emits z directly as packed split bf16 (GEMM1's A operand).
// ============================================================
__global__ void k_aggregate(const int* __restrict__ ei, const int* __restrict__ ea,
                            const float* __restrict__ bond,
                            const float* __restrict__ eps, int n, int layer)
{
    int w    = (blockIdx.x * blockDim.x + threadIdx.x) >> 5;
    int lane = threadIdx.x & 31;
    if (w >= n) return;
    int deg = g_fill[w];
    if (deg > DEG_CAP) deg = DEG_CAP;

    const float4* h4 = (const float4*)g_h;
    const float4* bl = (const float4*)(bond + (size_t)layer * 3 * 16 * D_);
    const int l2 = lane + 32, l3 = lane + 64;
    float4 a0 = make_float4(0.f, 0.f, 0.f, 0.f), a1 = a0, a2 = a0;

    const int* bucket = g_eid + (size_t)w * DEG_CAP;
    for (int p = 0; p < deg; ++p) {
        int eid = bucket[p];
        int src = ei[eid];
        int t3  = eid * 3;
        int c0 = ea[t3], c1 = ea[t3 + 1], c2 = ea[t3 + 2];
        const float4* hr = h4 + (size_t)src * 75;
        const float4* r0 = bl + c0 * 75;
        const float4* r1 = bl + (16 + c1) * 75;
        const float4* r2 = bl + (32 + c2) * 75;
        float4 h, e0, e1, e2;
        h = hr[lane]; e0 = r0[lane]; e1 = r1[lane]; e2 = r2[lane];
        a0.x += fmaxf(h.x + e0.x + e1.x + e2.x, 0.f);
        a0.y += fmaxf(h.y + e0.y + e1.y + e2.y, 0.f);
        a0.z += fmaxf(h.z + e0.z + e1.z + e2.z, 0.f);
        a0.w += fmaxf(h.w + e0.w + e1.w + e2.w, 0.f);
        h = hr[l2]; e0 = r0[l2]; e1 = r1[l2]; e2 = r2[l2];
        a1.x += fmaxf(h.x + e0.x + e1.x + e2.x, 0.f);
        a1.y += fmaxf(h.y + e0.y + e1.y + e2.y, 0.f);
        a1.z += fmaxf(h.z + e0.z + e1.z + e2.z, 0.f);
        a1.w += fmaxf(h.w + e0.w + e1.w + e2.w, 0.f);
        if (l3 < 75) {
            h = hr[l3]; e0 = r0[l3]; e1 = r1[l3]; e2 = r2[l3];
            a2.x += fmaxf(h.x + e0.x + e1.x + e2.x, 0.f);
            a2.y += fmaxf(h.y + e0.y + e1.y + e2.y, 0.f);
            a2.z += fmaxf(h.z + e0.z + e1.z + e2.z, 0.f);
            a2.w += fmaxf(h.w + e0.w + e1.w + e2.w, 0.f);
        }
    }
    float ep = 1.f + eps[layer];
    const float4* hv = h4 + (size_t)w * 75;
    const size_t rowbase = (size_t)w * KP2_1;
    float4 h, o;
    h = hv[lane];
    o.x = fmaf(ep, h.x, a0.x); o.y = fmaf(ep, h.y, a0.y);
    o.z = fmaf(ep, h.z, a0.z); o.w = fmaf(ep, h.w, a0.w);
    packw(g_a1h, g_a1l, rowbase, 2 * lane,     o.x, o.y);
    packw(g_a1h, g_a1l, rowbase, 2 * lane + 1, o.z, o.w);
    h = hv[l2];
    o.x = fmaf(ep, h.x, a1.x); o.y = fmaf(ep, h.y, a1.y);
    o.z = fmaf(ep, h.z, a1.z); o.w = fmaf(ep, h.w, a1.w);
    packw(g_a1h, g_a1l, rowbase, 2 * l2,     o.x, o.y);
    packw(g_a1h, g_a1l, rowbase, 2 * l2 + 1, o.z, o.w);
    if (l3 < 75) {
        h = hv[l3];
        o.x = fmaf(ep, h.x, a2.x); o.y = fmaf(ep, h.y, a2.y);
        o.z = fmaf(ep, h.z, a2.z); o.w = fmaf(ep, h.w, a2.w);
        packw(g_a1h, g_a1l, rowbase, 2 * l3,     o.x, o.y);
        packw(g_a1h, g_a1l, rowbase, 2 * l3 + 1, o.z, o.w);
    }
    if (lane < KP2_1 - 150)
        packw(g_a1h, g_a1l, rowbase, 150 + lane, 0.f, 0.f);
}

// ============================================================
// A-split for GEMM2: relu(BN1(h1)) -> packed split bf16
// ============================================================
__global__ void k_asplit(const float* __restrict__ X, int M, int K, int Kp2)
{
    int idx = blockIdx.x * blockDim.x + threadIdx.x;
    if (idx >= M * Kp2) return;
    int m   = idx / Kp2;
    int kp2 = idx - m * Kp2;
    int k0  = 2 * kp2;
    float a = 0.f, b = 0.f;
    if (k0 < K) {
        float2 v = *(const float2*)(X + (size_t)m * K + k0);
        a = fmaxf(fmaf(v.x, g_bnA[k0],     g_bnB[k0]),     0.f);
        b = fmaxf(fmaf(v.y, g_bnA[k0 + 1], g_bnB[k0 + 1]), 0.f);
    }
    packw(g_a2h, g_a2l, (size_t)m * Kp2, kp2, a, b);
}

// ============================================================
// 3xBF16 mma.sync GEMM: 256 threads, 8 warps (4x2), 32x32 warp tiles,
// BM=128 BN=64, swizzled smem, double-buffered, 3 CTAs/SM, fused stats.
// ============================================================
__global__ void __launch_bounds__(256, 3) k_gemm_mma(
    const uint32_t* __restrict__ Ah, const uint32_t* __restrict__ Al,
    const uint32_t* __restrict__ Bh, const uint32_t* __restrict__ Bl,
    const float* __restrict__ bias, float* __restrict__ C,
    int M, int Kpad, int NC)
{
    extern __shared__ uint32_t smu[];
    const int tid = threadIdx.x;
    const int wid = tid >> 5, lid = tid & 31;
    const int g = lid >> 2, t4 = lid & 3;
    const int wm = wid >> 1, wn = wid & 1;
    const int bm = blockIdx.y * BM, bn = blockIdx.x * BN;
    const int nch = Kpad / BK;
    const int Kp2 = Kpad >> 1;

    // loader mapping: lrow = tid>>2 (0..63), lc4 = tid&3 (16B slot)
    const int lrow = tid >> 2;
    const int lc4  = tid & 3;
    const int c4s  = lc4 ^ (lrow & 3);          // same for lrow and lrow+64
    const bool aOk0 = (bm + lrow) < M;
    const bool aOk1 = (bm + lrow + 64) < M;
    const uint32_t* AhR0 = Ah + (size_t)(bm + lrow) * Kp2 + lc4 * 4;
    const uint32_t* AlR0 = Al + (size_t)(bm + lrow) * Kp2 + lc4 * 4;
    const uint32_t* AhR1 = AhR0 + (size_t)64 * Kp2;
    const uint32_t* AlR1 = AlR0 + (size_t)64 * Kp2;
    const uint32_t* BhR  = Bh + (size_t)(bn + lrow) * Kp2 + lc4 * 4;
    const uint32_t* BlR  = Bl + (size_t)(bn + lrow) * Kp2 + lc4 * 4;
    const uint32_t sm32 = smem_u32(smu);
    const uint32_t stA0 = sm32 + (uint32_t)((AHO_U + lrow * STRU + c4s * 4) * 4);
    const uint32_t stA1 = stA0 + 64 * STRU * 4;
    const uint32_t stAl0 = stA0 + (ALO_U - AHO_U) * 4;
    const uint32_t stAl1 = stA1 + (ALO_U - AHO_U) * 4;
    const uint32_t stBh = sm32 + (uint32_t)((BHO_U + lrow * STRU + c4s * 4) * 4);
    const uint32_t stBl = stBh + (BLO_U - BHO_U) * 4;

    float acc[2][4][4];
#pragma unroll
    for (int i = 0; i < 2; i++)
#pragma unroll
        for (int j = 0; j < 4; j++)
#pragma unroll
            for (int k = 0; k < 4; k++) acc[i][j][k] = 0.f;

#define CP_CHUNK(BUFB, C0)                                                \
    {                                                                     \
        const uint32_t bo = (uint32_t)((BUFB) * 4);                       \
        const int co = (C0) * 16;                                         \
        cp16p(stA0 + bo,  AhR0 + co, aOk0);                               \
        cp16p(stA1 + bo,  AhR1 + co, aOk1);                               \
        cp16p(stAl0 + bo, AlR0 + co, aOk0);                               \
        cp16p(stAl1 + bo, AlR1 + co, aOk1);                               \
        cp16p(stBh + bo,  BhR + co,  true);                               \
        cp16p(stBl + bo,  BlR + co,  true);                               \
    }

    CP_CHUNK(0, 0);
    cp_commit();
    cp_wait0();
    __syncthreads();

    for (int c = 0; c < nch; ++c) {
        const int bufc = (c & 1) * BUFSZ_U;
        const int bufn = ((c + 1) & 1) * BUFSZ_U;
        if (c + 1 < nch) {
            CP_CHUNK(bufn, c + 1);
            cp_commit();
        }
        {
            const uint32_t* aH = smu + bufc + AHO_U;
            const uint32_t* aL = smu + bufc + ALO_U;
            const uint32_t* bH = smu + bufc + BHO_U;
            const uint32_t* bL = smu + bufc + BLO_U;
#pragma unroll
            for (int s = 0; s < 2; ++s) {
                const int c2s = (s * 4 + t4) ^ (2 * (g & 3));  // swizzled uint2 idx
                const int wo  = 2 * c2s;
                uint2 fbh[4], fbl[4];
#pragma unroll
                for (int nt = 0; nt < 4; ++nt) {
                    const int n = wn * 32 + nt * 8 + g;
                    fbh[nt] = *(const uint2*)(bH + n * STRU + wo);
                    fbl[nt] = *(const uint2*)(bL + n * STRU + wo);
                }
                uint2 ah0[2], ah1[2], al0[2], al1[2];
#pragma unroll
                for (int mt = 0; mt < 2; ++mt) {
                    const int r0 = wm * 32 + mt * 16 + g;
                    ah0[mt] = *(const uint2*)(aH + r0 * STRU + wo);
                    ah1[mt] = *(const uint2*)(aH + (r0 + 8) * STRU + wo);
                    al0[mt] = *(const uint2*)(aL + r0 * STRU + wo);
                    al1[mt] = *(const uint2*)(aL + (r0 + 8) * STRU + wo);
                }
#pragma unroll
                for (int mt = 0; mt < 2; ++mt)
#pragma unroll
                    for (int nt = 0; nt < 4; ++nt)
                        mma16(acc[mt][nt], ah0[mt].x, ah1[mt].x, ah0[mt].y, ah1[mt].y,
                              fbh[nt].x, fbh[nt].y);
#pragma unroll
                for (int mt = 0; mt < 2; ++mt)
#pragma unroll
                    for (int nt = 0; nt < 4; ++nt)
                        mma16(acc[mt][nt], ah0[mt].x, ah1[mt].x, ah0[mt].y, ah1[mt].y,
                              fbl[nt].x, fbl[nt].y);
#pragma unroll
                for (int mt = 0; mt < 2; ++mt)
#pragma unroll
                    for (int nt = 0; nt < 4; ++nt)
                        mma16(acc[mt][nt], al0[mt].x, al1[mt].x, al0[mt].y, al1[mt].y,
                              fbh[nt].x, fbh[nt].y);
            }
        }
        if (c + 1 < nch) cp_wait0();
        __syncthreads();
    }

    // ---- epilogue: +bias, stores, fused column stats ----
#pragma unroll
    for (int nt = 0; nt < 4; ++nt) {
        const int col = bn + wn * 32 + nt * 8 + 2 * t4;
        const bool cok = col < NC;
        const float b0 = cok ? bias[col]     : 0.f;
        const float b1 = cok ? bias[col + 1] : 0.f;
        float s0 = 0.f, s1 = 0.f, q0 = 0.f, q1 = 0.f;
#pragma unroll
        for (int mt = 0; mt < 2; ++mt) {
            const int r0g = bm + wm * 32 + mt * 16 + g;
            const float* a4 = acc[mt][nt];
            if (cok && r0g < M) {
                float v0 = a4[0] + b0, v1 = a4[1] + b1;
                *(float2*)(C + (size_t)r0g * NC + col) = make_float2(v0, v1);
                s0 += v0; q0 += v0 * v0;
                s1 += v1; q1 += v1 * v1;
            }
            if (cok && r0g + 8 < M) {
                float v2 = a4[2] + b0, v3 = a4[3] + b1;
                *(float2*)(C + (size_t)(r0g + 8) * NC + col) = make_float2(v2, v3);
                s0 += v2; q0 += v2 * v2;
                s1 += v3; q1 += v3 * v3;
            }
        }
#pragma unroll
        for (int m = 4; m <= 16; m <<= 1) {
            s0 += __shfl_xor_sync(0xffffffffu, s0, m);
            s1 += __shfl_xor_sync(0xffffffffu, s1, m);
            q0 += __shfl_xor_sync(0xffffffffu, q0, m);
            q1 += __shfl_xor_sync(0xffffffffu, q1, m);
        }
        if (cok && g == 0) {
            atomicAdd(&g_cs[col],     s0);
            atomicAdd(&g_cq[col],     q0);
            atomicAdd(&g_cs[col + 1], s1);
            atomicAdd(&g_cq[col + 1], q1);
        }
    }
#undef CP_CHUNK
}

// ============================================================
// BN finalize + apply
// ============================================================
__global__ void k_finalize(const float* __restrict__ g, const float* __restrict__ b,
                           int M, int C)
{
    int c = threadIdx.x;
    float mean = g_cs[c] / (float)M;
    float var  = g_cq[c] / (float)M - mean * mean;
    float a = g[c] * rsqrtf(var + 1e-5f);
    g_bnA[c] = a;
    g_bnB[c] = fmaf(-mean, a, b[c]);
}

__global__ void k_apply(int do_relu, int n, float* __restrict__ out)
{
    int idx = blockIdx.x * blockDim.x + threadIdx.x;
    if (idx >= n * D_) return;
    int c = idx % D_;
    float v = fmaf(g_z2[idx], g_bnA[c], g_bnB[c]);
    if (do_relu) v = fmaxf(v, 0.f);
    if (out) out[idx] = v;
    else     g_h[idx] = v;
}

// ============================================================
// Launch
// ============================================================
extern "C" void kernel_launch(void* const* d_in, const int* in_sizes, int n_in,
                              void* d_out, int out_size)
{
    const int*   x     = (const int*)  d_in[0];
    const int*   ei    = (const int*)  d_in[1];
    const int*   ea    = (const int*)  d_in[2];
    const float* atom  = (const float*)d_in[3];
    const float* bond  = (const float*)d_in[4];
    const float* eps   = (const float*)d_in[5];
    const float* W1    = (const float*)d_in[6];
    const float* b1    = (const float*)d_in[7];
    const float* g1    = (const float*)d_in[8];
    const float* be1   = (const float*)d_in[9];
    const float* W2    = (const float*)d_in[10];
    const float* b2    = (const float*)d_in[11];
    const float* gamma = (const float*)d_in[12];
    const float* beta  = (const float*)d_in[13];
    float* out = (float*)d_out;

    const int N = in_sizes[0] / 9;
    const int E = in_sizes[1] / 2;

    float *ph1, *pz2;
    uint32_t *pa1h, *pa1l, *pa2h, *pa2l, *pw1h, *pw1l, *pw2h, *pw2l;
    cudaGetSymbolAddress((void**)&ph1,  g_h1);
    cudaGetSymbolAddress((void**)&pz2,  g_z2);
    cudaGetSymbolAddress((void**)&pa1h, g_a1h);
    cudaGetSymbolAddress((void**)&pa1l, g_a1l);
    cudaGetSymbolAddress((void**)&pa2h, g_a2h);
    cudaGetSymbolAddress((void**)&pa2l, g_a2l);
    cudaGetSymbolAddress((void**)&pw1h, g_w1h);
    cudaGetSymbolAddress((void**)&pw1l, g_w1l);
    cudaGetSymbolAddress((void**)&pw2h, g_w2h);
    cudaGetSymbolAddress((void**)&pw2l, g_w2l);

    cudaFuncSetAttribute(k_gemm_mma, cudaFuncAttributeMaxDynamicSharedMemorySize,
                         GEMM_SMEM);

    const int TPB = 256;
    const int node_grid = (N * D_ + TPB - 1) / TPB;
    const int agg_grid  = (N + 7) / 8;
    const int asp_grid  = (N * KP2_2 + TPB - 1) / TPB;
    const dim3 g1grid(NCP1 / BN, (N + BM - 1) / BM);
    const dim3 g2grid(NCP2 / BN, (N + BM - 1) / BM);
    const int wp1 = (NCP1 * KP2_1 + TPB - 1) / TPB;
    const int wp2 = (NCP2 * KP2_2 + TPB - 1) / TPB;

    // #0: W1 prep (also zeroes stats + degree counters)
    k_wprep<<<wp1, TPB>>>(W1, pw1h, pw1l, D_, TWOD_, KP2_1, NCP1, 1);
    // #1: atom encoder + edge bucketing
    k_atom<<<node_grid, TPB>>>(x, atom, ei, N, E);

    for (int l = 0; l < 5; ++l) {
        if (l > 0)
            k_wprep<<<wp1, TPB>>>(W1 + (size_t)l * D_ * TWOD_, pw1h, pw1l,
                                  D_, TWOD_, KP2_1, NCP1, 0);
        // #2 (l=0): aggregation -> packed A1
        k_aggregate<<<agg_grid, TPB>>>(ei, ea, bond, eps, N, l);
        // #3 (l=0): h1 = z @ W1 + b1  (+ fused BN1 stats) — profiled slot
        k_gemm_mma<<<g1grid, TPB, GEMM_SMEM>>>(pa1h, pa1l, pw1h, pw1l,
                                               b1 + l * TWOD_, ph1,
                                               N, KPAD1, TWOD_);
        k_finalize<<<1, TWOD_>>>(g1 + l * TWOD_, be1 + l * TWOD_, N, TWOD_);
        // A2 = relu(BN1(h1)) packed split
        k_asplit<<<asp_grid, TPB>>>(ph1, N, TWOD_, KP2_2);
        k_wprep<<<wp2, TPB>>>(W2 + (size_t)l * TWOD_ * D_, pw2h, pw2l,
                              TWOD_, D_, KP2_2, NCP2, 0);
        // z2 = A2 @ W2 + b2  (+ fused BN2 stats)
        k_gemm_mma<<<g2grid, TPB, GEMM_SMEM>>>(pa2h, pa2l, pw2h, pw2l,
                                               b2 + l * D_, pz2,
                                               N, KPAD2, D_);
        k_finalize<<<1, D_>>>(gamma + l * D_, beta + l * D_, N, D_);
        // h = BN2(z2) (+relu) for next layer, or final output
        if (l < 4)
            k_apply<<<node_grid, TPB>>>(1, N, nullptr);
        else
            k_apply<<<node_grid, TPB>>>(0, N, out);
    }
}